// round 13
// baseline (speedup 1.0000x reference)
#include <cuda_runtime.h>

#define NN  50000
#define RR  50
#define BB  30
#define EE  1000000
// F_IN = H = 64, C = 8

// ---------------- device scratch ----------------
__device__ int   g_cnt[NN * RR];
__device__ int   g_relcnt[RR];
__device__ int   g_reloff[RR + 1];
__device__ int   g_cursor[RR];
__device__ int   g_done;
__device__ int   g_esrc[EE];        // meta in bucket order
__device__ int   g_edst[EE];
__device__ float g_es[EE];
__device__ float g_W0[RR * 64 * 64];
__device__ float g_W1[RR * 64 * 64];
__device__ float g_W2[RR * 64 * 8];
__device__ float g_h[NN * 64];
__device__ float g_msg[NN * 64];    // zero between uses (restored by k_combine)
__device__ float g_acc[NN * 64];

// ---------------- helpers ----------------
__device__ __forceinline__ void ffma2(unsigned long long& d,
                                      unsigned long long a,
                                      unsigned long long b) {
    asm("fma.rn.f32x2 %0, %1, %2, %0;" : "+l"(d) : "l"(a), "l"(b));
}
__device__ __forceinline__ float pairsum(unsigned long long d) {
    return __uint_as_float((unsigned)(d & 0xffffffffULL)) +
           __uint_as_float((unsigned)(d >> 32));
}
__device__ __forceinline__ unsigned long long packf2(float a, float b) {
    return (unsigned long long)__float_as_uint(a) |
           ((unsigned long long)__float_as_uint(b) << 32);
}
__device__ __forceinline__ void cp16(void* s, const void* g) {
    unsigned sa = (unsigned)__cvta_generic_to_shared(s);
    asm volatile("cp.async.cg.shared.global [%0], [%1], 16;\n" :: "r"(sa), "l"(g));
}
__device__ __forceinline__ void cp_commit() { asm volatile("cp.async.commit_group;\n"); }
template <int N>
__device__ __forceinline__ void cp_wait() {
    asm volatile("cp.async.wait_group %0;\n" :: "n"(N));
}
__device__ __forceinline__ void barsync64(int id) {
    asm volatile("bar.sync %0, 64;\n" :: "r"(id) : "memory");
}

// ---------------- setup ----------------
__global__ void k_zero() {
    for (int i = blockIdx.x * blockDim.x + threadIdx.x; i < NN * RR;
         i += gridDim.x * blockDim.x)
        g_cnt[i] = 0;
    if (blockIdx.x == 0 && threadIdx.x < RR) g_relcnt[threadIdx.x] = 0;
}

// y==0: histogram (+ last block computes prefix scan)
// y==1/2/3: fold W for layers 0/1/2 (independent of hist)
__global__ void k_histW(const int* __restrict__ ei, const int* __restrict__ et,
                        const float* __restrict__ comp0, const float* __restrict__ bases0,
                        const float* __restrict__ comp1, const float* __restrict__ bases1,
                        const float* __restrict__ comp2, const float* __restrict__ bases2) {
    if (blockIdx.y == 0) {
        __shared__ int sh[RR];
        if (threadIdx.x < RR) sh[threadIdx.x] = 0;
        __syncthreads();
        for (int e = blockIdx.x * blockDim.x + threadIdx.x; e < EE;
             e += gridDim.x * blockDim.x) {
            int d = ei[EE + e];
            int r = et[e];
            atomicAdd(&g_cnt[d * RR + r], 1);
            atomicAdd(&sh[r], 1);
        }
        __syncthreads();
        if (threadIdx.x < RR) atomicAdd(&g_relcnt[threadIdx.x], sh[threadIdx.x]);
        __threadfence();
        if (threadIdx.x == 0) {
            int t = atomicAdd(&g_done, 1);
            if (t == gridDim.x - 1) {       // last hist block: do the scan
                int acc = 0;
                for (int r = 0; r < RR; r++) {
                    g_reloff[r] = acc;
                    g_cursor[r] = acc;
                    acc += g_relcnt[r];
                }
                g_reloff[RR] = acc;
                g_done = 0;                 // reset for next graph replay
                __threadfence();
            }
        }
    } else {
        const float* comp  = blockIdx.y == 1 ? comp0  : (blockIdx.y == 2 ? comp1  : comp2);
        const float* bases = blockIdx.y == 1 ? bases0 : (blockIdx.y == 2 ? bases1 : bases2);
        float* W  = blockIdx.y == 1 ? g_W0 : (blockIdx.y == 2 ? g_W1 : g_W2);
        int dout  = blockIdx.y == 3 ? 8 : 64;
        int total = RR * 64 * dout;
        for (int idx = blockIdx.x * blockDim.x + threadIdx.x; idx < total;
             idx += gridDim.x * blockDim.x) {
            int r = idx / (64 * dout);
            int rem = idx % (64 * dout);
            int i = rem / dout;
            int o = rem % dout;
            float w = 0.0f;
            #pragma unroll 6
            for (int b = 0; b < BB; b++)
                w = fmaf(comp[r * BB + b], bases[(b * 64 + i) * dout + o], w);
            W[idx] = w;
        }
    }
}

// bucket edges by relation, writing flat meta (src/dst/scale) directly
#define PCHUNK 4096
__global__ void k_permmeta(const int* __restrict__ ei, const int* __restrict__ et) {
    __shared__ int scnt[RR], sbase[RR], soff[RR];
    int lo = blockIdx.x * PCHUNK;
    int hi = min(lo + PCHUNK, EE);
    if (threadIdx.x < RR) { scnt[threadIdx.x] = 0; soff[threadIdx.x] = 0; }
    __syncthreads();
    for (int e = lo + threadIdx.x; e < hi; e += blockDim.x)
        atomicAdd(&scnt[et[e]], 1);
    __syncthreads();
    if (threadIdx.x < RR)
        sbase[threadIdx.x] = atomicAdd(&g_cursor[threadIdx.x], scnt[threadIdx.x]);
    __syncthreads();
    for (int e = lo + threadIdx.x; e < hi; e += blockDim.x) {
        int r = et[e];
        int p = sbase[r] + atomicAdd(&soff[r], 1);
        int s = ei[e], d = ei[EE + e];
        g_esrc[p] = s;
        g_edst[p] = d;
        g_es[p] = 1.0f / (float)g_cnt[d * RR + r];
    }
}

// ---------------- edge kernels ----------------
// 64-out edge transform: 64-thread groups, 8-edge batches, DEPTH-3 cp.async
// pipeline, ONE named barrier per 8 edges. Each WARP handles 4 edges of the
// batch; each thread computes 2 outputs (lane, lane+32) so the x-row is read
// once per warp (halves LDS wavefronts vs 1-output scheme). f32x2 FMA.
__global__ __launch_bounds__(128, 3) void k_edge64(const float* __restrict__ xin,
                                                   const float* __restrict__ Wall,
                                                   float* __restrict__ msg, int ngroups) {
    constexpr int BATCH = 8;
    constexpr int DEPTH = 3;
    int r = blockIdx.y;
    int lo = g_reloff[r], hi = g_reloff[r + 1];
    int cnt = hi - lo;
    int group = threadIdx.x >> 6;           // 2 groups per 128-thread block
    int gt = threadIdx.x & 63;              // thread within group
    int wid = gt >> 5;                      // warp within group (0/1)
    int lane = gt & 31;
    int gid = (blockIdx.x << 1) + group;
    int chunk = (cnt + ngroups - 1) / ngroups;
    int gbeg = lo + gid * chunk;
    int n = min(chunk, hi - gbeg);          // group-uniform; may be <= 0
    int nb = (n + BATCH - 1) / BATCH;       // batches (may be <= 0)

    // weights for outputs `lane` and `lane+32`, packed along k
    const float* Wr = Wall + (r << 12);
    unsigned long long wlo[32], whi[32];
    #pragma unroll
    for (int i = 0; i < 32; i++) {
        wlo[i] = packf2(Wr[(2 * i) * 64 + lane],      Wr[(2 * i + 1) * 64 + lane]);
        whi[i] = packf2(Wr[(2 * i) * 64 + lane + 32], Wr[(2 * i + 1) * 64 + lane + 32]);
    }

    __shared__ __align__(16) float xs[2][DEPTH][BATCH][64];
    __shared__ int   sdst[2][DEPTH][BATCH];
    __shared__ float ssc[2][DEPTH][BATCH];

    int j8 = gt >> 3;            // edge within batch this thread gathers (0..7)
    int h8 = gt & 7;             // 32B chunk within the row

    auto issue = [&](int t) {
        if (t < nb) {
            int slot = t % DEPTH;
            int base = gbeg + t * BATCH;
            int idx = base + j8;
            if (idx < gbeg + n) {
                int src = __ldg(&g_esrc[idx]);
                const float* xp = xin + ((size_t)src << 6) + (h8 << 3);
                float* sp = &xs[group][slot][j8][h8 << 3];
                cp16(sp, xp);
                cp16(sp + 4, xp + 4);
            }
            if (gt >= 48) {
                int j = gt & 7;
                int mi = base + j;
                if (mi < gbeg + n) {
                    if (gt < 56) sdst[group][slot][j] = __ldg(&g_edst[mi]);
                    else         ssc[group][slot][j]  = __ldg(&g_es[mi]);
                }
            }
        }
        cp_commit();
    };

    issue(0); issue(1);
    for (int t = 0; t < nb; t++) {
        int slot = t % DEPTH;
        cp_wait<1>();
        barsync64(group + 1);               // batch t visible; batch t-1 consumed
        int nj = min(BATCH, n - t * BATCH);
        #pragma unroll
        for (int jj = 0; jj < 4; jj++) {
            int j = (wid << 2) + jj;        // warp 0: edges 0-3, warp 1: edges 4-7
            if (j < nj) {
                int dst = sdst[group][slot][j];
                float s = ssc[group][slot][j];
                const ulonglong2* xv = (const ulonglong2*)xs[group][slot][j];
                unsigned long long a0 = 0, a1 = 0, b0 = 0, b1 = 0;
                #pragma unroll
                for (int i = 0; i < 16; i++) {
                    ulonglong2 v = xv[i];
                    ffma2(a0, v.x, wlo[2 * i]);
                    ffma2(a1, v.y, wlo[2 * i + 1]);
                    ffma2(b0, v.x, whi[2 * i]);
                    ffma2(b1, v.y, whi[2 * i + 1]);
                }
                atomicAdd(&msg[(dst << 6) + lane],      s * (pairsum(a0) + pairsum(a1)));
                atomicAdd(&msg[(dst << 6) + lane + 32], s * (pairsum(b0) + pairsum(b1)));
            }
        }
        issue(t + 2);                       // slot (t+2)%3 free: consumed before this bar
    }
}

// 8-out edge transform: warp-private pipeline, 4 edges per warp iteration.
__global__ __launch_bounds__(256, 2) void k_edge8(const float* __restrict__ xin,
                                                  float* __restrict__ msg, int nw) {
    constexpr int DEPTH = 4;
    int r = blockIdx.y;
    int lo = g_reloff[r], hi = g_reloff[r + 1];
    int cnt = hi - lo;
    int w = threadIdx.x >> 5;
    int lane = threadIdx.x & 31;
    int q = lane >> 3, o = lane & 7;
    int wid = (blockIdx.x << 3) + w;
    int chunk = (cnt + nw - 1) / nw;
    int wbeg = lo + wid * chunk;
    int n = min(chunk, hi - wbeg);
    int iters = (n + 3) >> 2;

    const float* Wr = g_W2 + r * 512;
    unsigned long long w2[32];
    #pragma unroll
    for (int i = 0; i < 32; i++)
        w2[i] = packf2(Wr[(2 * i) * 8 + o], Wr[(2 * i + 1) * 8 + o]);

    __shared__ __align__(16) float xs[8][DEPTH][4][68];
    __shared__ int   sdst[8][DEPTH][4];
    __shared__ float ssc[8][DEPTH][4];

    auto issue = [&](int it) {
        if (it < iters) {
            int slot = it & 3;
            int base = wbeg + (it << 2);
            #pragma unroll
            for (int c = lane; c < 64; c += 32) {
                int eq = c >> 4, p = c & 15;
                int idx = base + eq;
                if (idx < wbeg + n) {
                    int src = __ldg(&g_esrc[idx]);
                    cp16(&xs[w][slot][eq][p << 2], xin + ((size_t)src << 6) + (p << 2));
                }
            }
            if (lane < 4) {
                int idx = base + lane;
                if (idx < wbeg + n) {
                    sdst[w][slot][lane] = __ldg(&g_edst[idx]);
                    ssc[w][slot][lane]  = __ldg(&g_es[idx]);
                }
            }
        }
        cp_commit();
    };

    issue(0); issue(1); issue(2);
    for (int it = 0; it < iters; it++) {
        int slot = it & 3;
        cp_wait<2>();
        __syncwarp();
        int idx = wbeg + (it << 2) + q;
        if (idx < wbeg + n) {
            int dst = sdst[w][slot][q];
            float s = ssc[w][slot][q];
            const ulonglong2* xv = (const ulonglong2*)xs[w][slot][q];
            unsigned long long a0 = 0, a1 = 0;
            #pragma unroll
            for (int i = 0; i < 16; i++) {
                ulonglong2 v = xv[i];
                ffma2(a0, v.x, w2[2 * i]);
                ffma2(a1, v.y, w2[2 * i + 1]);
            }
            atomicAdd(&msg[(dst << 3) + o], s * (pairsum(a0) + pairsum(a1)));
        }
        issue(it + 3);
    }
}

// ---------------- epilogue ----------------
__global__ void k_combine(const float* __restrict__ xin, const float* __restrict__ root,
                          const float* __restrict__ bias, float* __restrict__ msgio,
                          float* __restrict__ outp, int dout, int relu) {
    int idx = blockIdx.x * blockDim.x + threadIdx.x;
    if (idx >= NN * dout) return;
    int nd = idx / dout, o = idx - nd * dout;
    float s = bias[o] + msgio[idx];
    msgio[idx] = 0.0f;
    const float4* xr = (const float4*)(xin + (nd << 6));
    #pragma unroll
    for (int i = 0; i < 16; i++) {
        float4 v = xr[i];
        s = fmaf(v.x, root[(4 * i + 0) * dout + o], s);
        s = fmaf(v.y, root[(4 * i + 1) * dout + o], s);
        s = fmaf(v.z, root[(4 * i + 2) * dout + o], s);
        s = fmaf(v.w, root[(4 * i + 3) * dout + o], s);
    }
    outp[idx] = relu ? fmaxf(s, 0.0f) : s;
}

__global__ void k_lsm(const float* __restrict__ acc, float* __restrict__ outp) {
    int n = blockIdx.x * blockDim.x + threadIdx.x;
    if (n >= NN) return;
    float v[8];
    #pragma unroll
    for (int c = 0; c < 8; c++) v[c] = acc[n * 8 + c];
    float m = v[0];
    #pragma unroll
    for (int c = 1; c < 8; c++) m = fmaxf(m, v[c]);
    float ssum = 0.0f;
    #pragma unroll
    for (int c = 0; c < 8; c++) ssum += expf(v[c] - m);
    float l = m + logf(ssum);
    #pragma unroll
    for (int c = 0; c < 8; c++) outp[n * 8 + c] = v[c] - l;
}

// ---------------- launch ----------------
extern "C" void kernel_launch(void* const* d_in, const int* in_sizes, int n_in,
                              void* d_out, int out_size) {
    const float* x      = (const float*)d_in[0];
    const int*   ei     = (const int*)d_in[1];
    const int*   et     = (const int*)d_in[2];
    const float* bases0 = (const float*)d_in[3];
    const float* comp0  = (const float*)d_in[4];
    const float* root0  = (const float*)d_in[5];
    const float* bias0  = (const float*)d_in[6];
    const float* bases1 = (const float*)d_in[7];
    const float* comp1  = (const float*)d_in[8];
    const float* root1  = (const float*)d_in[9];
    const float* bias1  = (const float*)d_in[10];
    const float* bases2 = (const float*)d_in[11];
    const float* comp2  = (const float*)d_in[12];
    const float* root2  = (const float*)d_in[13];
    const float* bias2  = (const float*)d_in[14];
    float* out = (float*)d_out;

    float *pH = nullptr, *pMsg = nullptr, *pAcc = nullptr, *pW0, *pW1;
    cudaGetSymbolAddress((void**)&pH, g_h);
    cudaGetSymbolAddress((void**)&pMsg, g_msg);
    cudaGetSymbolAddress((void**)&pAcc, g_acc);
    cudaGetSymbolAddress((void**)&pW0, g_W0);
    cudaGetSymbolAddress((void**)&pW1, g_W1);

    const int GX = 24;   // edge64: groups per relation = GX*2 (128-thread blocks)
    const int GX8 = 8;   // edge8: warps per relation = GX8*8

    // setup: 3 launches so the first k_edge64 is launch index 3 (ncu window)
    k_zero<<<2048, 256>>>();
    k_histW<<<dim3(512, 4), 256>>>(ei, et, comp0, bases0, comp1, bases1, comp2, bases2);
    k_permmeta<<<(EE + PCHUNK - 1) / PCHUNK, 256>>>(ei, et);

    // layer 0
    k_edge64<<<dim3(GX, RR), 128>>>(x, pW0, pMsg, GX * 2);
    k_combine<<<(NN * 64 + 255) / 256, 256>>>(x, root0, bias0, pMsg, pH, 64, 1);

    // layer 1
    k_edge64<<<dim3(GX, RR), 128>>>(pH, pW1, pMsg, GX * 2);
    k_combine<<<(NN * 64 + 255) / 256, 256>>>(pH, root1, bias1, pMsg, pAcc, 64, 1);

    // layer 2 (64 -> 8) + log_softmax
    k_edge8<<<dim3(GX8, RR), 256>>>(pAcc, pMsg, GX8 * 8);
    k_combine<<<(NN * 8 + 255) / 256, 256>>>(pAcc, root2, bias2, pMsg, pH, 8, 0);
    k_lsm<<<(NN + 255) / 256, 256>>>(pH, out);
}